// round 15
// baseline (speedup 1.0000x reference)
#include <cuda_runtime.h>
#include <cuda_bf16.h>
#include <cstdint>

#define N_USER   6144
#define NTOT     12288
#define D        64
#define BATCH    2048
#define NNEG     8192
#define MAXF     2049
#define MAXU     10240
#define UBASE    2176                 // 17 F-tiles * 128
#define SLOTS    (UBASE + MAXU)
#define KT       32                   // K per stage
#define NSPF     16                   // F splits: 768 K each
#define NSPU     8                    // U splits: 768 K each
#define KSPL     768
#define NKT      24
#define F_ITEMS  (17 * NSPF)          // 272
#define U_ITEMS  (80 * NSPU)          // 640
#define NSTAGE   3
#define ASTR     40                   // fp32 units
#define BSTR     40                   // bf16 units
#define NPREB    (NTOT / 64)          // 192 pre blocks

// ---- dynamic smem byte offsets (k_main) ----
#define A_OFF    0
#define ASTAGE   20480                // 128*40*4
#define BH_OFF   (ASTAGE * NSTAGE)            // 61440
#define BSTAGE   5120                 // 64*40*2
#define BL_OFF   (BH_OFF + BSTAGE * NSTAGE)   // 76800
#define ROWP_OFF (BL_OFF + BSTAGE * NSTAGE)   // 92160
#define SM_TOTAL (ROWP_OFF + 128 * 8)         // 93184

// -------- device scratch (16B-aligned: accessed via float4/uint2) --------
__device__ __align__(16) float g_ego[NTOT * D];
__device__ __align__(16) __nv_bfloat16 g_eThi[(size_t)D * NTOT];
__device__ __align__(16) __nv_bfloat16 g_eTlo[(size_t)D * NTOT];
__device__ __align__(16) __nv_bfloat16 g_eMhi[(size_t)D * NTOT];
__device__ __align__(16) __nv_bfloat16 g_eMlo[(size_t)D * NTOT];
__device__ int g_listF[MAXF], g_listU[MAXU], g_pos[NTOT];
__device__ int g_cF, g_cU;
__device__ __align__(16) float g_part[NSPF][(size_t)SLOTS * D];

__device__ __forceinline__ uint32_t smem_u32(const void* p) {
    uint32_t a;
    asm("{ .reg .u64 t; cvta.to.shared.u64 t, %1; cvt.u32.u64 %0, t; }" : "=r"(a) : "l"(p));
    return a;
}
__device__ __forceinline__ void cp16cg(uint32_t dst, const void* src) {
    asm volatile("cp.async.cg.shared.global [%0], [%1], 16;" :: "r"(dst), "l"(src));
}
#define CP_COMMIT() asm volatile("cp.async.commit_group;" ::: "memory")
#define CP_WAIT(n)  asm volatile("cp.async.wait_group %0;" :: "n"(n) : "memory")

__device__ __forceinline__ void ldmx4(uint32_t* r, uint32_t addr) {
    asm volatile("ldmatrix.sync.aligned.m8n8.x4.shared.b16 {%0,%1,%2,%3}, [%4];"
                 : "=r"(r[0]), "=r"(r[1]), "=r"(r[2]), "=r"(r[3]) : "r"(addr));
}
__device__ __forceinline__ void mma16816(float* c, const uint32_t* a, const uint32_t* b) {
    asm volatile("mma.sync.aligned.m16n8k16.row.col.f32.bf16.bf16.f32 "
                 "{%0,%1,%2,%3},{%4,%5,%6,%7},{%8,%9},{%0,%1,%2,%3};"
                 : "+f"(c[0]), "+f"(c[1]), "+f"(c[2]), "+f"(c[3])
                 : "r"(a[0]), "r"(a[1]), "r"(a[2]), "r"(a[3]), "r"(b[0]), "r"(b[1]));
}
__device__ __forceinline__ void split2(float2 x, uint32_t& h, uint32_t& l) {
    __nv_bfloat162 hb = __float22bfloat162_rn(x);
    float2 hf = __bfloat1622float2(hb);
    __nv_bfloat162 lb = __float22bfloat162_rn(make_float2(x.x - hf.x, x.y - hf.y));
    h = *(uint32_t*)&hb; l = *(uint32_t*)&lb;
}

// -------- 1. fused prep: blocks 0..191 transpose+convert; block 192 compacts --------
__global__ void __launch_bounds__(1024) k_prep(const float* __restrict__ ue,
                                               const float* __restrict__ ie,
                                               const int* __restrict__ users,
                                               const int* __restrict__ pos,
                                               const int* __restrict__ neg) {
    int tid = threadIdx.x;

    if (blockIdx.x == NPREB) {
        // ---- compaction block (independent of pre blocks) ----
        __shared__ unsigned char cflag[NTOT], cneed[NTOT];
        __shared__ int warpF[32], warpU[32];
        __shared__ int baseF, baseU;
        int lane = tid & 31, wid = tid >> 5;
#pragma unroll
        for (int i = 0; i < NTOT / 4096; ++i) {
            ((uint32_t*)cflag)[tid + i * 1024] = 0;
            ((uint32_t*)cneed)[tid + i * 1024] = 0;
        }
        if (tid == 0) { baseF = 0; baseU = 0; }
        __syncthreads();
        if (tid == 0) cflag[users[0]] = 1;
        for (int i = tid; i < NNEG; i += 1024) cneed[N_USER + neg[i]] = 1;
        for (int i = tid; i < BATCH; i += 1024) {
            int rp = N_USER + pos[i];
            cflag[rp] = 1; cneed[rp] = 1;
            cneed[users[i]] = 1;
        }
        __syncthreads();
        for (int base = 0; base < NTOT; base += 1024) {
            int i = base + tid;
            int f = cflag[i];
            int u = (!f) && cneed[i];
            unsigned bf = __ballot_sync(0xFFFFFFFFu, f);
            unsigned bu = __ballot_sync(0xFFFFFFFFu, u);
            if (lane == 0) { warpF[wid] = __popc(bf); warpU[wid] = __popc(bu); }
            __syncthreads();
            int offF = baseF, offU = baseU;
            for (int k = 0; k < wid; ++k) { offF += warpF[k]; offU += warpU[k]; }
            if (f) {
                int j = offF + __popc(bf & ((1u << lane) - 1u));
                g_listF[j] = i; g_pos[i] = j;
            }
            if (u) {
                int j = offU + __popc(bu & ((1u << lane) - 1u));
                g_listU[j] = i; g_pos[i] = UBASE + j;
            }
            __syncthreads();
            if (tid == 0)
                for (int k = 0; k < 32; ++k) { baseF += warpF[k]; baseU += warpU[k]; }
            __syncthreads();
        }
        if (tid == 0) { g_cF = baseF; g_cU = baseU; }
        return;
    }

    // ---- pre block: self-computed flags, transpose + bf16 hi/lo ----
    __shared__ float tile[64][65];
    __shared__ unsigned char pflag[64];
    int k0 = blockIdx.x * 64;
    bool upper = (k0 >= N_USER);
    if (tid < 64) pflag[tid] = 0;
    __syncthreads();
    if (upper) {
        // flags in upper half come only from pos (users[0] < N_USER always)
        for (int i = tid; i < BATCH; i += 1024) {
            int rp = N_USER + pos[i] - k0;
            if ((unsigned)rp < 64u) pflag[rp] = 1;
        }
    }
    const float* src = upper ? (ie + (size_t)(k0 - N_USER) * D) : (ue + (size_t)k0 * D);
    {
        int k = tid >> 4, ng = tid & 15;
        float4 v = *(const float4*)(src + (size_t)k * D + ng * 4);
        tile[k][ng * 4 + 0] = v.x;
        tile[k][ng * 4 + 1] = v.y;
        tile[k][ng * 4 + 2] = v.z;
        tile[k][ng * 4 + 3] = v.w;
        *(float4*)(g_ego + (size_t)(k0 + k) * D + ng * 4) = v;
    }
    __syncthreads();
    __nv_bfloat16 z = __float2bfloat16(0.f);
    {
        int n = tid >> 4, kg = tid & 15;
        int k = kg * 4;
        uint32_t vh[2], vl[2], vmh[2], vml[2];
#pragma unroll
        for (int j = 0; j < 2; ++j) {
            float x0 = tile[k + 2 * j][n];
            float x1 = tile[k + 2 * j + 1][n];
            __nv_bfloat16 h0 = __float2bfloat16(x0), h1 = __float2bfloat16(x1);
            __nv_bfloat16 l0 = __float2bfloat16(x0 - __bfloat162float(h0));
            __nv_bfloat16 l1 = __float2bfloat16(x1 - __bfloat162float(h1));
            __nv_bfloat162 hp = __halves2bfloat162(h0, h1);
            __nv_bfloat162 lp = __halves2bfloat162(l0, l1);
            vh[j] = *(uint32_t*)&hp; vl[j] = *(uint32_t*)&lp;
            bool f0 = pflag[k + 2 * j] != 0, f1 = pflag[k + 2 * j + 1] != 0;
            __nv_bfloat162 mhp = __halves2bfloat162(f0 ? h0 : z, f1 ? h1 : z);
            __nv_bfloat162 mlp = __halves2bfloat162(f0 ? l0 : z, f1 ? l1 : z);
            vmh[j] = *(uint32_t*)&mhp; vml[j] = *(uint32_t*)&mlp;
        }
        size_t o = (size_t)n * NTOT + k0 + k;
        *(uint2*)(g_eThi + o) = make_uint2(vh[0], vh[1]);
        *(uint2*)(g_eTlo + o) = make_uint2(vl[0], vl[1]);
        if (upper) {
            *(uint2*)(g_eMhi + o) = make_uint2(vmh[0], vmh[1]);
            *(uint2*)(g_eMlo + o) = make_uint2(vml[0], vml[1]);
        }
    }
}

// -------- 2. main GEMM: 32x32 warp tiles, 3-stage cp.async.cg pipeline --------
__global__ void __launch_bounds__(256, 2) k_main(const float* __restrict__ adj) {
    extern __shared__ char sm[];
    uint32_t smb = smem_u32(sm);
    const float** sRow = (const float**)(sm + ROWP_OFF);

    int tid = threadIdx.x, wid = tid >> 5, lane = tid & 31;
    int cF = g_cF, cU = g_cU;
    int bx = blockIdx.x;

    int slotBase, j0, cnt, split;
    size_t kbase;
    const int* list;
    const __nv_bfloat16 *bh, *bl;
    if (bx < F_ITEMS) {
        int tile = bx >> 4; split = bx & (NSPF - 1);
        if (tile * 128 >= cF) return;
        j0 = tile * 128; slotBase = j0; list = g_listF; cnt = cF;
        bh = g_eThi; bl = g_eTlo;
        kbase = (size_t)split * KSPL;
    } else {
        int u = bx - F_ITEMS;
        int tile = u >> 3; split = u & (NSPU - 1);
        if (tile * 128 >= cU) return;
        j0 = tile * 128; slotBase = UBASE + j0; list = g_listU; cnt = cU;
        bh = g_eMhi; bl = g_eMlo;
        kbase = (size_t)N_USER + (size_t)split * KSPL;
    }

    if (tid < 128) {
        int j = j0 + tid; if (j >= cnt) j = cnt - 1;
        sRow[tid] = adj + (size_t)list[j] * NTOT + kbase;
    }
    __syncthreads();

    // ---- A staging map ----
    int r0s = tid >> 3, chs = tid & 7;
    const float* apj[4];
#pragma unroll
    for (int j = 0; j < 4; ++j) apj[j] = sRow[r0s + 32 * j] + chs * 4;
    uint32_t aDst = smb + A_OFF + (uint32_t)(r0s * ASTR + chs * 4) * 4;

    // ---- B staging map ----
    int bn = tid >> 2, bc = tid & 3;
    const __nv_bfloat16* bsrcH = bh + kbase + (size_t)bn * NTOT + bc * 8;
    const __nv_bfloat16* bsrcL = bl + kbase + (size_t)bn * NTOT + bc * 8;
    uint32_t bDstH = smb + BH_OFF + (uint32_t)(bn * BSTR + bc * 8) * 2;
    uint32_t bDstL = smb + BL_OFF + (uint32_t)(bn * BSTR + bc * 8) * 2;

    // ---- compute-side addressing: warp tile = 32 rows x 32 cols ----
    int mg = wid >> 1;
    int nh = wid & 1;
    const float* aBase = (const float*)(sm + A_OFF);
    int frow0 = mg * 32 + (lane >> 2);
    const float* aR0 = aBase + frow0 * ASTR + (lane & 3) * 2;
    const float* aR1 = aR0 + 8 * ASTR;
    const float* aR2 = aR0 + 16 * ASTR;
    const float* aR3 = aR0 + 24 * ASTR;
    uint32_t bLm = (uint32_t)(((nh * 32 + (lane & 7) + ((lane >> 4) << 3)) * BSTR
                               + ((lane >> 3) & 1) * 8) * 2);

    float acc[2][4][4];
#pragma unroll
    for (int mb = 0; mb < 2; ++mb)
#pragma unroll
        for (int nb = 0; nb < 4; ++nb)
#pragma unroll
            for (int i = 0; i < 4; ++i) acc[mb][nb][i] = 0.f;

    // ---- prologue: stages 0,1 ----
#pragma unroll
    for (int s = 0; s < 2; ++s) {
        uint32_t ad = aDst + s * ASTAGE;
        size_t ko = (size_t)s * KT;
#pragma unroll
        for (int j = 0; j < 4; ++j) cp16cg(ad + j * (32 * ASTR * 4), apj[j] + ko);
        cp16cg(bDstH + s * BSTAGE, bsrcH + ko);
        cp16cg(bDstL + s * BSTAGE, bsrcL + ko);
        CP_COMMIT();
    }

    for (int kt = 0; kt < NKT; ++kt) {
        int buf = kt % NSTAGE;
        CP_WAIT(1);
        __syncthreads();
        if (kt + 2 < NKT) {
            int s = (kt + 2) % NSTAGE;
            uint32_t ad = aDst + s * ASTAGE;
            size_t ko = (size_t)(kt + 2) * KT;
#pragma unroll
            for (int j = 0; j < 4; ++j) cp16cg(ad + j * (32 * ASTR * 4), apj[j] + ko);
            cp16cg(bDstH + s * BSTAGE, bsrcH + ko);
            cp16cg(bDstL + s * BSTAGE, bsrcL + ko);
        }
        CP_COMMIT();

        int abufo = buf * (ASTAGE / 4);
        uint32_t bh_base = smb + BH_OFF + buf * BSTAGE + bLm;
        uint32_t bl_base = smb + BL_OFF + buf * BSTAGE + bLm;

#pragma unroll
        for (int ks = 0; ks < 2; ++ks) {
            int ko = ks * 16;
            uint32_t ahf[2][4], alf[2][4];
            {
                float2 x0 = *(const float2*)(aR0 + abufo + ko);
                float2 x1 = *(const float2*)(aR1 + abufo + ko);
                float2 x2 = *(const float2*)(aR0 + abufo + ko + 8);
                float2 x3 = *(const float2*)(aR1 + abufo + ko + 8);
                split2(x0, ahf[0][0], alf[0][0]);
                split2(x1, ahf[0][1], alf[0][1]);
                split2(x2, ahf[0][2], alf[0][2]);
                split2(x3, ahf[0][3], alf[0][3]);
                x0 = *(const float2*)(aR2 + abufo + ko);
                x1 = *(const float2*)(aR3 + abufo + ko);
                x2 = *(const float2*)(aR2 + abufo + ko + 8);
                x3 = *(const float2*)(aR3 + abufo + ko + 8);
                split2(x0, ahf[1][0], alf[1][0]);
                split2(x1, ahf[1][1], alf[1][1]);
                split2(x2, ahf[1][2], alf[1][2]);
                split2(x3, ahf[1][3], alf[1][3]);
            }
            uint32_t bhf[4][2], blf[4][2];
            {
                uint32_t r[4];
                ldmx4(r, bh_base + ks * 32);
                bhf[0][0] = r[0]; bhf[0][1] = r[1]; bhf[1][0] = r[2]; bhf[1][1] = r[3];
                ldmx4(r, bh_base + 16 * BSTR * 2 + ks * 32);
                bhf[2][0] = r[0]; bhf[2][1] = r[1]; bhf[3][0] = r[2]; bhf[3][1] = r[3];
                ldmx4(r, bl_base + ks * 32);
                blf[0][0] = r[0]; blf[0][1] = r[1]; blf[1][0] = r[2]; blf[1][1] = r[3];
                ldmx4(r, bl_base + 16 * BSTR * 2 + ks * 32);
                blf[2][0] = r[0]; blf[2][1] = r[1]; blf[3][0] = r[2]; blf[3][1] = r[3];
            }
#pragma unroll
            for (int mb = 0; mb < 2; ++mb)
#pragma unroll
                for (int nb = 0; nb < 4; ++nb) {
                    mma16816(acc[mb][nb], ahf[mb], bhf[nb]);
                    mma16816(acc[mb][nb], ahf[mb], blf[nb]);
                    mma16816(acc[mb][nb], alf[mb], bhf[nb]);
                }
        }
    }

    float* dst = g_part[split];
#pragma unroll
    for (int mb = 0; mb < 2; ++mb) {
        int r0 = slotBase + mg * 32 + mb * 16 + (lane >> 2);
#pragma unroll
        for (int nb = 0; nb < 4; ++nb) {
            int col = nh * 32 + nb * 8 + (lane & 3) * 2;
            *(float2*)(dst + (size_t)r0 * D + col)       = make_float2(acc[mb][nb][0], acc[mb][nb][1]);
            *(float2*)(dst + (size_t)(r0 + 8) * D + col) = make_float2(acc[mb][nb][2], acc[mb][nb][3]);
        }
    }
}

// -------- 3. gather: 8 threads/q, 2 float4 each; deterministic reduction --------
__global__ void k_gather(const float* __restrict__ adj,
                         const int* __restrict__ users, const int* __restrict__ pos,
                         const int* __restrict__ neg, float* __restrict__ out) {
    int t = blockIdx.x * 256 + threadIdx.x;    // t < 12288 * 8
    int q = t >> 3, j = t & 7;
    int ds0 = j * 4, ds1 = j * 4 + 32;
    int r;
    if (q < BATCH)          r = users[q];
    else if (q < 2 * BATCH) r = N_USER + pos[q - BATCH];
    else                    r = N_USER + neg[q - 2 * BATCH];
    int p = g_pos[r];
    size_t o0 = (size_t)p * D + ds0, o1 = (size_t)p * D + ds1;
    float4 s0 = make_float4(0.f, 0.f, 0.f, 0.f);
    float4 s1 = make_float4(0.f, 0.f, 0.f, 0.f);
    if (p < UBASE) {
#pragma unroll
        for (int k = 0; k < NSPF; ++k) {
            float4 v0 = *(const float4*)(g_part[k] + o0);
            float4 v1 = *(const float4*)(g_part[k] + o1);
            s0.x += v0.x; s0.y += v0.y; s0.z += v0.z; s0.w += v0.w;
            s1.x += v1.x; s1.y += v1.y; s1.z += v1.z; s1.w += v1.w;
        }
    } else {
#pragma unroll
        for (int k = 0; k < NSPU; ++k) {
            float4 v0 = *(const float4*)(g_part[k] + o0);
            float4 v1 = *(const float4*)(g_part[k] + o1);
            s0.x += v0.x; s0.y += v0.y; s0.z += v0.z; s0.w += v0.w;
            s1.x += v1.x; s1.y += v1.y; s1.z += v1.z; s1.w += v1.w;
        }
        int u0 = users[0];
        float a = adj[(size_t)r * NTOT + u0];
        float4 e0 = *(const float4*)(g_ego + (size_t)u0 * D + ds0);
        float4 e1 = *(const float4*)(g_ego + (size_t)u0 * D + ds1);
        s0.x += a * e0.x; s0.y += a * e0.y; s0.z += a * e0.z; s0.w += a * e0.w;
        s1.x += a * e1.x; s1.y += a * e1.y; s1.z += a * e1.z; s1.w += a * e1.w;
    }
    float4 eg0 = *(const float4*)(g_ego + (size_t)r * D + ds0);
    float4 eg1 = *(const float4*)(g_ego + (size_t)r * D + ds1);
    float4 r0, r1;
    r0.x = 0.25f * (eg0.x + 3.0f * s0.x);
    r0.y = 0.25f * (eg0.y + 3.0f * s0.y);
    r0.z = 0.25f * (eg0.z + 3.0f * s0.z);
    r0.w = 0.25f * (eg0.w + 3.0f * s0.w);
    r1.x = 0.25f * (eg1.x + 3.0f * s1.x);
    r1.y = 0.25f * (eg1.y + 3.0f * s1.y);
    r1.z = 0.25f * (eg1.z + 3.0f * s1.z);
    r1.w = 0.25f * (eg1.w + 3.0f * s1.w);
    *(float4*)(out + (size_t)q * D + ds0) = r0;
    *(float4*)(out + (size_t)q * D + ds1) = r1;
}

extern "C" void kernel_launch(void* const* d_in, const int* in_sizes, int n_in,
                              void* d_out, int out_size) {
    const float* adj   = (const float*)d_in[0];
    const float* ue    = (const float*)d_in[1];
    const float* ie    = (const float*)d_in[2];
    const int*   users = (const int*)d_in[3];
    const int*   pos   = (const int*)d_in[4];
    const int*   neg   = (const int*)d_in[5];
    float*       out   = (float*)d_out;

    cudaFuncSetAttribute(k_main, cudaFuncAttributeMaxDynamicSharedMemorySize, SM_TOTAL);

    k_prep<<<NPREB + 1, 1024>>>(ue, ie, users, pos, neg);
    k_main<<<F_ITEMS + U_ITEMS, 256, SM_TOTAL>>>(adj);
    k_gather<<<(6 * BATCH * D / 8) / 256, 256>>>(adj, users, pos, neg, out);
}

// round 16
// speedup vs baseline: 1.0514x; 1.0514x over previous
#include <cuda_runtime.h>
#include <cuda_bf16.h>
#include <cstdint>

#define N_USER   6144
#define NTOT     12288
#define D        64
#define BATCH    2048
#define NNEG     8192
#define MAXF     2049
#define MAXU     10240
#define UBASE    2176                 // 17 F-tiles * 128
#define SLOTS    (UBASE + MAXU)
#define KT       32                   // K per stage
#define NSPF     16                   // F splits: 768 K each
#define NSPU     8                    // U splits: 768 K each
#define KSPL     768
#define NKT      24
#define F_ITEMS  (17 * NSPF)          // 272
#define U_ITEMS  (80 * NSPU)          // 640
#define NSTAGE   3
#define ASTR     40                   // fp32 units
#define BSTR     40                   // bf16 units
#define NPREB    (NTOT / 64)          // 192 pre blocks

// ---- dynamic smem byte offsets (k_main) ----
#define A_OFF    0
#define ASTAGE   20480                // 128*40*4
#define BH_OFF   (ASTAGE * NSTAGE)            // 61440
#define BSTAGE   5120                 // 64*40*2
#define BL_OFF   (BH_OFF + BSTAGE * NSTAGE)   // 76800
#define ROWP_OFF (BL_OFF + BSTAGE * NSTAGE)   // 92160
#define SM_TOTAL (ROWP_OFF + 128 * 8)         // 93184

// -------- device scratch (16B-aligned: accessed via float4/uint2) --------
__device__ __align__(16) float g_ego[NTOT * D];
__device__ __align__(16) __nv_bfloat16 g_eThi[(size_t)D * NTOT];
__device__ __align__(16) __nv_bfloat16 g_eTlo[(size_t)D * NTOT];
__device__ __align__(16) __nv_bfloat16 g_eMhi[(size_t)D * NTOT];
__device__ __align__(16) __nv_bfloat16 g_eMlo[(size_t)D * NTOT];
__device__ int g_listF[MAXF], g_listU[MAXU], g_pos[NTOT];
__device__ int g_cF, g_cU;
__device__ __align__(16) float g_part[NSPF][(size_t)SLOTS * D];

__device__ __forceinline__ uint32_t smem_u32(const void* p) {
    uint32_t a;
    asm("{ .reg .u64 t; cvta.to.shared.u64 t, %1; cvt.u32.u64 %0, t; }" : "=r"(a) : "l"(p));
    return a;
}
__device__ __forceinline__ void cp16cg(uint32_t dst, const void* src) {
    asm volatile("cp.async.cg.shared.global [%0], [%1], 16;" :: "r"(dst), "l"(src));
}
#define CP_COMMIT() asm volatile("cp.async.commit_group;" ::: "memory")
#define CP_WAIT(n)  asm volatile("cp.async.wait_group %0;" :: "n"(n) : "memory")

__device__ __forceinline__ void ldmx4(uint32_t* r, uint32_t addr) {
    asm volatile("ldmatrix.sync.aligned.m8n8.x4.shared.b16 {%0,%1,%2,%3}, [%4];"
                 : "=r"(r[0]), "=r"(r[1]), "=r"(r[2]), "=r"(r[3]) : "r"(addr));
}
__device__ __forceinline__ void mma16816(float* c, const uint32_t* a, const uint32_t* b) {
    asm volatile("mma.sync.aligned.m16n8k16.row.col.f32.bf16.bf16.f32 "
                 "{%0,%1,%2,%3},{%4,%5,%6,%7},{%8,%9},{%0,%1,%2,%3};"
                 : "+f"(c[0]), "+f"(c[1]), "+f"(c[2]), "+f"(c[3])
                 : "r"(a[0]), "r"(a[1]), "r"(a[2]), "r"(a[3]), "r"(b[0]), "r"(b[1]));
}
__device__ __forceinline__ void split2(float2 x, uint32_t& h, uint32_t& l) {
    __nv_bfloat162 hb = __float22bfloat162_rn(x);
    float2 hf = __bfloat1622float2(hb);
    __nv_bfloat162 lb = __float22bfloat162_rn(make_float2(x.x - hf.x, x.y - hf.y));
    h = *(uint32_t*)&hb; l = *(uint32_t*)&lb;
}

// -------- 1. fused prep: blocks 0..191 transpose+convert; block 192 compacts --------
__global__ void __launch_bounds__(1024) k_prep(const float* __restrict__ ue,
                                               const float* __restrict__ ie,
                                               const int* __restrict__ users,
                                               const int* __restrict__ pos,
                                               const int* __restrict__ neg) {
    int tid = threadIdx.x;

    if (blockIdx.x == NPREB) {
        // ---- compaction block (parallel warp-scan prefix) ----
        __shared__ unsigned char cflag[NTOT], cneed[NTOT];
        __shared__ int warpF[32], warpU[32];
        __shared__ int baseF, baseU;
        int lane = tid & 31, wid = tid >> 5;
#pragma unroll
        for (int i = 0; i < NTOT / 4096; ++i) {
            ((uint32_t*)cflag)[tid + i * 1024] = 0;
            ((uint32_t*)cneed)[tid + i * 1024] = 0;
        }
        if (tid == 0) { baseF = 0; baseU = 0; }
        __syncthreads();
        if (tid == 0) cflag[users[0]] = 1;
        for (int i = tid; i < NNEG; i += 1024) cneed[N_USER + neg[i]] = 1;
        for (int i = tid; i < BATCH; i += 1024) {
            int rp = N_USER + pos[i];
            cflag[rp] = 1; cneed[rp] = 1;
            cneed[users[i]] = 1;
        }
        __syncthreads();
        for (int base = 0; base < NTOT; base += 1024) {
            int i = base + tid;
            int f = cflag[i];
            int u = (!f) && cneed[i];
            unsigned bf = __ballot_sync(0xFFFFFFFFu, f);
            unsigned bu = __ballot_sync(0xFFFFFFFFu, u);
            if (lane == 0) { warpF[wid] = __popc(bf); warpU[wid] = __popc(bu); }
            __syncthreads();
            if (wid == 0) {
                int bF = baseF, bU = baseU;
                int oF = warpF[lane], oU = warpU[lane];
                int vF = oF, vU = oU;
#pragma unroll
                for (int d = 1; d < 32; d <<= 1) {
                    int tF = __shfl_up_sync(0xFFFFFFFFu, vF, d);
                    int tU = __shfl_up_sync(0xFFFFFFFFu, vU, d);
                    if (lane >= d) { vF += tF; vU += tU; }
                }
                warpF[lane] = bF + vF - oF;   // exclusive prefix + base
                warpU[lane] = bU + vU - oU;
                if (lane == 31) { baseF = bF + vF; baseU = bU + vU; }
            }
            __syncthreads();
            if (f) {
                int j = warpF[wid] + __popc(bf & ((1u << lane) - 1u));
                g_listF[j] = i; g_pos[i] = j;
            }
            if (u) {
                int j = warpU[wid] + __popc(bu & ((1u << lane) - 1u));
                g_listU[j] = i; g_pos[i] = UBASE + j;
            }
            __syncthreads();
        }
        if (tid == 0) { g_cF = baseF; g_cU = baseU; }
        return;
    }

    // ---- pre block: self-computed flags, transpose + bf16 hi/lo ----
    __shared__ float tile[64][65];
    __shared__ unsigned char pflag[64];
    int k0 = blockIdx.x * 64;
    bool upper = (k0 >= N_USER);
    if (tid < 64) pflag[tid] = 0;
    __syncthreads();
    if (upper) {
        // flags in upper half come only from pos (users[0] < N_USER always)
        for (int i = tid; i < BATCH; i += 1024) {
            int rp = N_USER + pos[i] - k0;
            if ((unsigned)rp < 64u) pflag[rp] = 1;
        }
    }
    const float* src = upper ? (ie + (size_t)(k0 - N_USER) * D) : (ue + (size_t)k0 * D);
    {
        int k = tid >> 4, ng = tid & 15;
        float4 v = *(const float4*)(src + (size_t)k * D + ng * 4);
        tile[k][ng * 4 + 0] = v.x;
        tile[k][ng * 4 + 1] = v.y;
        tile[k][ng * 4 + 2] = v.z;
        tile[k][ng * 4 + 3] = v.w;
        *(float4*)(g_ego + (size_t)(k0 + k) * D + ng * 4) = v;
    }
    __syncthreads();
    __nv_bfloat16 z = __float2bfloat16(0.f);
    {
        int n = tid >> 4, kg = tid & 15;
        int k = kg * 4;
        uint32_t vh[2], vl[2], vmh[2], vml[2];
#pragma unroll
        for (int j = 0; j < 2; ++j) {
            float x0 = tile[k + 2 * j][n];
            float x1 = tile[k + 2 * j + 1][n];
            __nv_bfloat16 h0 = __float2bfloat16(x0), h1 = __float2bfloat16(x1);
            __nv_bfloat16 l0 = __float2bfloat16(x0 - __bfloat162float(h0));
            __nv_bfloat16 l1 = __float2bfloat16(x1 - __bfloat162float(h1));
            __nv_bfloat162 hp = __halves2bfloat162(h0, h1);
            __nv_bfloat162 lp = __halves2bfloat162(l0, l1);
            vh[j] = *(uint32_t*)&hp; vl[j] = *(uint32_t*)&lp;
            bool f0 = pflag[k + 2 * j] != 0, f1 = pflag[k + 2 * j + 1] != 0;
            __nv_bfloat162 mhp = __halves2bfloat162(f0 ? h0 : z, f1 ? h1 : z);
            __nv_bfloat162 mlp = __halves2bfloat162(f0 ? l0 : z, f1 ? l1 : z);
            vmh[j] = *(uint32_t*)&mhp; vml[j] = *(uint32_t*)&mlp;
        }
        size_t o = (size_t)n * NTOT + k0 + k;
        *(uint2*)(g_eThi + o) = make_uint2(vh[0], vh[1]);
        *(uint2*)(g_eTlo + o) = make_uint2(vl[0], vl[1]);
        if (upper) {
            *(uint2*)(g_eMhi + o) = make_uint2(vmh[0], vmh[1]);
            *(uint2*)(g_eMlo + o) = make_uint2(vml[0], vml[1]);
        }
    }
}

// -------- 2. main GEMM: 32x32 warp tiles, 3-stage cp.async.cg pipeline --------
__global__ void __launch_bounds__(256, 2) k_main(const float* __restrict__ adj) {
    extern __shared__ char sm[];
    uint32_t smb = smem_u32(sm);
    const float** sRow = (const float**)(sm + ROWP_OFF);

    int tid = threadIdx.x, wid = tid >> 5, lane = tid & 31;
    int cF = g_cF, cU = g_cU;
    int bx = blockIdx.x;

    int slotBase, j0, cnt, split;
    size_t kbase;
    const int* list;
    const __nv_bfloat16 *bh, *bl;
    if (bx < F_ITEMS) {
        int tile = bx >> 4; split = bx & (NSPF - 1);
        if (tile * 128 >= cF) return;
        j0 = tile * 128; slotBase = j0; list = g_listF; cnt = cF;
        bh = g_eThi; bl = g_eTlo;
        kbase = (size_t)split * KSPL;
    } else {
        int u = bx - F_ITEMS;
        int tile = u >> 3; split = u & (NSPU - 1);
        if (tile * 128 >= cU) return;
        j0 = tile * 128; slotBase = UBASE + j0; list = g_listU; cnt = cU;
        bh = g_eMhi; bl = g_eMlo;
        kbase = (size_t)N_USER + (size_t)split * KSPL;
    }

    if (tid < 128) {
        int j = j0 + tid; if (j >= cnt) j = cnt - 1;
        sRow[tid] = adj + (size_t)list[j] * NTOT + kbase;
    }
    __syncthreads();

    // ---- A staging map ----
    int r0s = tid >> 3, chs = tid & 7;
    const float* apj[4];
#pragma unroll
    for (int j = 0; j < 4; ++j) apj[j] = sRow[r0s + 32 * j] + chs * 4;
    uint32_t aDst = smb + A_OFF + (uint32_t)(r0s * ASTR + chs * 4) * 4;

    // ---- B staging map ----
    int bn = tid >> 2, bc = tid & 3;
    const __nv_bfloat16* bsrcH = bh + kbase + (size_t)bn * NTOT + bc * 8;
    const __nv_bfloat16* bsrcL = bl + kbase + (size_t)bn * NTOT + bc * 8;
    uint32_t bDstH = smb + BH_OFF + (uint32_t)(bn * BSTR + bc * 8) * 2;
    uint32_t bDstL = smb + BL_OFF + (uint32_t)(bn * BSTR + bc * 8) * 2;

    // ---- compute-side addressing: warp tile = 32 rows x 32 cols ----
    int mg = wid >> 1;
    int nh = wid & 1;
    const float* aBase = (const float*)(sm + A_OFF);
    int frow0 = mg * 32 + (lane >> 2);
    const float* aR0 = aBase + frow0 * ASTR + (lane & 3) * 2;
    const float* aR1 = aR0 + 8 * ASTR;
    const float* aR2 = aR0 + 16 * ASTR;
    const float* aR3 = aR0 + 24 * ASTR;
    uint32_t bLm = (uint32_t)(((nh * 32 + (lane & 7) + ((lane >> 4) << 3)) * BSTR
                               + ((lane >> 3) & 1) * 8) * 2);

    float acc[2][4][4];
#pragma unroll
    for (int mb = 0; mb < 2; ++mb)
#pragma unroll
        for (int nb = 0; nb < 4; ++nb)
#pragma unroll
            for (int i = 0; i < 4; ++i) acc[mb][nb][i] = 0.f;

    // ---- prologue: stages 0,1 ----
#pragma unroll
    for (int s = 0; s < 2; ++s) {
        uint32_t ad = aDst + s * ASTAGE;
        size_t ko = (size_t)s * KT;
#pragma unroll
        for (int j = 0; j < 4; ++j) cp16cg(ad + j * (32 * ASTR * 4), apj[j] + ko);
        cp16cg(bDstH + s * BSTAGE, bsrcH + ko);
        cp16cg(bDstL + s * BSTAGE, bsrcL + ko);
        CP_COMMIT();
    }

    for (int kt = 0; kt < NKT; ++kt) {
        int buf = kt % NSTAGE;
        CP_WAIT(1);
        __syncthreads();
        if (kt + 2 < NKT) {
            int s = (kt + 2) % NSTAGE;
            uint32_t ad = aDst + s * ASTAGE;
            size_t ko = (size_t)(kt + 2) * KT;
#pragma unroll
            for (int j = 0; j < 4; ++j) cp16cg(ad + j * (32 * ASTR * 4), apj[j] + ko);
            cp16cg(bDstH + s * BSTAGE, bsrcH + ko);
            cp16cg(bDstL + s * BSTAGE, bsrcL + ko);
        }
        CP_COMMIT();

        int abufo = buf * (ASTAGE / 4);
        uint32_t bh_base = smb + BH_OFF + buf * BSTAGE + bLm;
        uint32_t bl_base = smb + BL_OFF + buf * BSTAGE + bLm;

#pragma unroll
        for (int ks = 0; ks < 2; ++ks) {
            int ko = ks * 16;
            uint32_t ahf[2][4], alf[2][4];
            {
                float2 x0 = *(const float2*)(aR0 + abufo + ko);
                float2 x1 = *(const float2*)(aR1 + abufo + ko);
                float2 x2 = *(const float2*)(aR0 + abufo + ko + 8);
                float2 x3 = *(const float2*)(aR1 + abufo + ko + 8);
                split2(x0, ahf[0][0], alf[0][0]);
                split2(x1, ahf[0][1], alf[0][1]);
                split2(x2, ahf[0][2], alf[0][2]);
                split2(x3, ahf[0][3], alf[0][3]);
                x0 = *(const float2*)(aR2 + abufo + ko);
                x1 = *(const float2*)(aR3 + abufo + ko);
                x2 = *(const float2*)(aR2 + abufo + ko + 8);
                x3 = *(const float2*)(aR3 + abufo + ko + 8);
                split2(x0, ahf[1][0], alf[1][0]);
                split2(x1, ahf[1][1], alf[1][1]);
                split2(x2, ahf[1][2], alf[1][2]);
                split2(x3, ahf[1][3], alf[1][3]);
            }
            uint32_t bhf[4][2], blf[4][2];
            {
                uint32_t r[4];
                ldmx4(r, bh_base + ks * 32);
                bhf[0][0] = r[0]; bhf[0][1] = r[1]; bhf[1][0] = r[2]; bhf[1][1] = r[3];
                ldmx4(r, bh_base + 16 * BSTR * 2 + ks * 32);
                bhf[2][0] = r[0]; bhf[2][1] = r[1]; bhf[3][0] = r[2]; bhf[3][1] = r[3];
                ldmx4(r, bl_base + ks * 32);
                blf[0][0] = r[0]; blf[0][1] = r[1]; blf[1][0] = r[2]; blf[1][1] = r[3];
                ldmx4(r, bl_base + 16 * BSTR * 2 + ks * 32);
                blf[2][0] = r[0]; blf[2][1] = r[1]; blf[3][0] = r[2]; blf[3][1] = r[3];
            }
#pragma unroll
            for (int mb = 0; mb < 2; ++mb)
#pragma unroll
                for (int nb = 0; nb < 4; ++nb) {
                    mma16816(acc[mb][nb], ahf[mb], bhf[nb]);
                    mma16816(acc[mb][nb], ahf[mb], blf[nb]);
                    mma16816(acc[mb][nb], alf[mb], bhf[nb]);
                }
        }
    }

    float* dst = g_part[split];
#pragma unroll
    for (int mb = 0; mb < 2; ++mb) {
        int r0 = slotBase + mg * 32 + mb * 16 + (lane >> 2);
#pragma unroll
        for (int nb = 0; nb < 4; ++nb) {
            int col = nh * 32 + nb * 8 + (lane & 3) * 2;
            *(float2*)(dst + (size_t)r0 * D + col)       = make_float2(acc[mb][nb][0], acc[mb][nb][1]);
            *(float2*)(dst + (size_t)(r0 + 8) * D + col) = make_float2(acc[mb][nb][2], acc[mb][nb][3]);
        }
    }
}

// -------- 3. gather: 8 threads/q, 2 float4 each; deterministic reduction --------
__global__ void k_gather(const float* __restrict__ adj,
                         const int* __restrict__ users, const int* __restrict__ pos,
                         const int* __restrict__ neg, float* __restrict__ out) {
    int t = blockIdx.x * 256 + threadIdx.x;    // t < 12288 * 8
    int q = t >> 3, j = t & 7;
    int ds0 = j * 4, ds1 = j * 4 + 32;
    int r;
    if (q < BATCH)          r = users[q];
    else if (q < 2 * BATCH) r = N_USER + pos[q - BATCH];
    else                    r = N_USER + neg[q - 2 * BATCH];
    int p = g_pos[r];
    size_t o0 = (size_t)p * D + ds0, o1 = (size_t)p * D + ds1;
    float4 s0 = make_float4(0.f, 0.f, 0.f, 0.f);
    float4 s1 = make_float4(0.f, 0.f, 0.f, 0.f);
    if (p < UBASE) {
#pragma unroll
        for (int k = 0; k < NSPF; ++k) {
            float4 v0 = *(const float4*)(g_part[k] + o0);
            float4 v1 = *(const float4*)(g_part[k] + o1);
            s0.x += v0.x; s0.y += v0.y; s0.z += v0.z; s0.w += v0.w;
            s1.x += v1.x; s1.y += v1.y; s1.z += v1.z; s1.w += v1.w;
        }
    } else {
#pragma unroll
        for (int k = 0; k < NSPU; ++k) {
            float4 v0 = *(const float4*)(g_part[k] + o0);
            float4 v1 = *(const float4*)(g_part[k] + o1);
            s0.x += v0.x; s0.y += v0.y; s0.z += v0.z; s0.w += v0.w;
            s1.x += v1.x; s1.y += v1.y; s1.z += v1.z; s1.w += v1.w;
        }
        int u0 = users[0];
        float a = adj[(size_t)r * NTOT + u0];
        float4 e0 = *(const float4*)(g_ego + (size_t)u0 * D + ds0);
        float4 e1 = *(const float4*)(g_ego + (size_t)u0 * D + ds1);
        s0.x += a * e0.x; s0.y += a * e0.y; s0.z += a * e0.z; s0.w += a * e0.w;
        s1.x += a * e1.x; s1.y += a * e1.y; s1.z += a * e1.z; s1.w += a * e1.w;
    }
    float4 eg0 = *(const float4*)(g_ego + (size_t)r * D + ds0);
    float4 eg1 = *(const float4*)(g_ego + (size_t)r * D + ds1);
    float4 r0, r1;
    r0.x = 0.25f * (eg0.x + 3.0f * s0.x);
    r0.y = 0.25f * (eg0.y + 3.0f * s0.y);
    r0.z = 0.25f * (eg0.z + 3.0f * s0.z);
    r0.w = 0.25f * (eg0.w + 3.0f * s0.w);
    r1.x = 0.25f * (eg1.x + 3.0f * s1.x);
    r1.y = 0.25f * (eg1.y + 3.0f * s1.y);
    r1.z = 0.25f * (eg1.z + 3.0f * s1.z);
    r1.w = 0.25f * (eg1.w + 3.0f * s1.w);
    *(float4*)(out + (size_t)q * D + ds0) = r0;
    *(float4*)(out + (size_t)q * D + ds1) = r1;
}

extern "C" void kernel_launch(void* const* d_in, const int* in_sizes, int n_in,
                              void* d_out, int out_size) {
    const float* adj   = (const float*)d_in[0];
    const float* ue    = (const float*)d_in[1];
    const float* ie    = (const float*)d_in[2];
    const int*   users = (const int*)d_in[3];
    const int*   pos   = (const int*)d_in[4];
    const int*   neg   = (const int*)d_in[5];
    float*       out   = (float*)d_out;

    cudaFuncSetAttribute(k_main, cudaFuncAttributeMaxDynamicSharedMemorySize, SM_TOTAL);

    k_prep<<<NPREB + 1, 1024>>>(ue, ie, users, pos, neg);
    k_main<<<F_ITEMS + U_ITEMS, 256, SM_TOTAL>>>(adj);
    k_gather<<<(6 * BATCH * D / 8) / 256, 256>>>(adj, users, pos, neg, out);
}

// round 17
// speedup vs baseline: 1.0691x; 1.0169x over previous
#include <cuda_runtime.h>
#include <cuda_bf16.h>
#include <cstdint>

#define N_USER   6144
#define NTOT     12288
#define D        64
#define BATCH    2048
#define NNEG     8192
#define MAXF     2049
#define MAXU     10240
#define UBASE    2176                 // 17 F-tiles * 128
#define SLOTS    (UBASE + MAXU)
#define KT       32                   // K per stage
#define NSPF     16                   // F splits: 768 K each
#define NSPU     8                    // U splits: 768 K each
#define KSPL     768
#define NKT      24
#define F_ITEMS  (17 * NSPF)          // 272
#define U_ITEMS  (80 * NSPU)          // 640
#define NSTAGE   3
#define ASTR     40                   // fp32 units
#define BSTR     40                   // bf16 units
#define NPREB    (NTOT / 64)          // 192 pre blocks
#define NRND     (NTOT / 1024)        // 12 compaction rounds

// ---- dynamic smem byte offsets (k_main) ----
#define A_OFF    0
#define ASTAGE   20480                // 128*40*4
#define BH_OFF   (ASTAGE * NSTAGE)            // 61440
#define BSTAGE   5120                 // 64*40*2
#define BL_OFF   (BH_OFF + BSTAGE * NSTAGE)   // 76800
#define ROWP_OFF (BL_OFF + BSTAGE * NSTAGE)   // 92160
#define SM_TOTAL (ROWP_OFF + 128 * 8)         // 93184

// -------- device scratch (16B-aligned: accessed via float4/uint2) --------
__device__ __align__(16) float g_ego[NTOT * D];
__device__ __align__(16) __nv_bfloat16 g_eThi[(size_t)D * NTOT];
__device__ __align__(16) __nv_bfloat16 g_eTlo[(size_t)D * NTOT];
__device__ __align__(16) __nv_bfloat16 g_eMhi[(size_t)D * NTOT];
__device__ __align__(16) __nv_bfloat16 g_eMlo[(size_t)D * NTOT];
__device__ int g_listF[MAXF], g_listU[MAXU], g_pos[NTOT];
__device__ int g_cF, g_cU;
__device__ __align__(16) float g_part[NSPF][(size_t)SLOTS * D];

__device__ __forceinline__ uint32_t smem_u32(const void* p) {
    uint32_t a;
    asm("{ .reg .u64 t; cvta.to.shared.u64 t, %1; cvt.u32.u64 %0, t; }" : "=r"(a) : "l"(p));
    return a;
}
__device__ __forceinline__ void cp16cg(uint32_t dst, const void* src) {
    asm volatile("cp.async.cg.shared.global [%0], [%1], 16;" :: "r"(dst), "l"(src));
}
#define CP_COMMIT() asm volatile("cp.async.commit_group;" ::: "memory")
#define CP_WAIT(n)  asm volatile("cp.async.wait_group %0;" :: "n"(n) : "memory")

__device__ __forceinline__ void ldmx4(uint32_t* r, uint32_t addr) {
    asm volatile("ldmatrix.sync.aligned.m8n8.x4.shared.b16 {%0,%1,%2,%3}, [%4];"
                 : "=r"(r[0]), "=r"(r[1]), "=r"(r[2]), "=r"(r[3]) : "r"(addr));
}
__device__ __forceinline__ void mma16816(float* c, const uint32_t* a, const uint32_t* b) {
    asm volatile("mma.sync.aligned.m16n8k16.row.col.f32.bf16.bf16.f32 "
                 "{%0,%1,%2,%3},{%4,%5,%6,%7},{%8,%9},{%0,%1,%2,%3};"
                 : "+f"(c[0]), "+f"(c[1]), "+f"(c[2]), "+f"(c[3])
                 : "r"(a[0]), "r"(a[1]), "r"(a[2]), "r"(a[3]), "r"(b[0]), "r"(b[1]));
}
__device__ __forceinline__ void split2(float2 x, uint32_t& h, uint32_t& l) {
    __nv_bfloat162 hb = __float22bfloat162_rn(x);
    float2 hf = __bfloat1622float2(hb);
    __nv_bfloat162 lb = __float22bfloat162_rn(make_float2(x.x - hf.x, x.y - hf.y));
    h = *(uint32_t*)&hb; l = *(uint32_t*)&lb;
}

// -------- 1. fused prep: blocks 0..191 transpose+convert; block 192 compacts --------
__global__ void __launch_bounds__(1024) k_prep(const float* __restrict__ ue,
                                               const float* __restrict__ ie,
                                               const int* __restrict__ users,
                                               const int* __restrict__ pos,
                                               const int* __restrict__ neg) {
    __shared__ union U {
        struct {
            unsigned char cflag[NTOT], cneed[NTOT];
            unsigned balF[NRND][32], balU[NRND][32];
            int offF[NRND][32], offU[NRND][32];
        } c;
        struct {
            float tile[64][65];
            unsigned char pflag[64];
        } p;
        __device__ U() {}
    } sh;
    int tid = threadIdx.x;

    if (blockIdx.x == NPREB) {
        // ---- compaction block: 3 barrier-phases total ----
        int lane = tid & 31, wid = tid >> 5;
#pragma unroll
        for (int i = 0; i < NTOT / 4096; ++i) {
            ((uint32_t*)sh.c.cflag)[tid + i * 1024] = 0;
            ((uint32_t*)sh.c.cneed)[tid + i * 1024] = 0;
        }
        __syncthreads();
        if (tid == 0) sh.c.cflag[users[0]] = 1;
        for (int i = tid; i < NNEG; i += 1024) sh.c.cneed[N_USER + neg[i]] = 1;
        for (int i = tid; i < BATCH; i += 1024) {
            int rp = N_USER + pos[i];
            sh.c.cflag[rp] = 1; sh.c.cneed[rp] = 1;
            sh.c.cneed[users[i]] = 1;
        }
        __syncthreads();
        // phase 1: all ballots, no barriers
#pragma unroll
        for (int r = 0; r < NRND; ++r) {
            int i = r * 1024 + tid;
            int f = sh.c.cflag[i];
            int u = (!f) && sh.c.cneed[i];
            unsigned bf = __ballot_sync(0xFFFFFFFFu, f);
            unsigned bu = __ballot_sync(0xFFFFFFFFu, u);
            if (lane == 0) { sh.c.balF[r][wid] = bf; sh.c.balU[r][wid] = bu; }
        }
        __syncthreads();
        // phase 2: warp 0 ordered exclusive scan over 384 (r,w) counts
        if (wid == 0) {
            int myF[NRND], myU[NRND];
            int sF = 0, sU = 0;
#pragma unroll
            for (int k = 0; k < NRND; ++k) {
                int fl = lane * NRND + k;
                int r = fl >> 5, w = fl & 31;
                myF[k] = sF; myU[k] = sU;
                sF += __popc(sh.c.balF[r][w]);
                sU += __popc(sh.c.balU[r][w]);
            }
            int iF = sF, iU = sU;
#pragma unroll
            for (int d = 1; d < 32; d <<= 1) {
                int tF = __shfl_up_sync(0xFFFFFFFFu, iF, d);
                int tU = __shfl_up_sync(0xFFFFFFFFu, iU, d);
                if (lane >= d) { iF += tF; iU += tU; }
            }
            int exF = iF - sF, exU = iU - sU;   // exclusive lane prefix
#pragma unroll
            for (int k = 0; k < NRND; ++k) {
                int fl = lane * NRND + k;
                int r = fl >> 5, w = fl & 31;
                sh.c.offF[r][w] = exF + myF[k];
                sh.c.offU[r][w] = exU + myU[k];
            }
            if (lane == 31) { g_cF = iF; g_cU = iU; }
        }
        __syncthreads();
        // phase 3: all scatters, no barriers
        unsigned mybit = 1u << (tid & 31);
#pragma unroll
        for (int r = 0; r < NRND; ++r) {
            int i = r * 1024 + tid;
            unsigned bf = sh.c.balF[r][wid], bu = sh.c.balU[r][wid];
            if (bf & mybit) {
                int j = sh.c.offF[r][wid] + __popc(bf & (mybit - 1));
                g_listF[j] = i; g_pos[i] = j;
            }
            if (bu & mybit) {
                int j = sh.c.offU[r][wid] + __popc(bu & (mybit - 1));
                g_listU[j] = i; g_pos[i] = UBASE + j;
            }
        }
        return;
    }

    // ---- pre block: self-computed flags, transpose + bf16 hi/lo ----
    int k0 = blockIdx.x * 64;
    bool upper = (k0 >= N_USER);
    if (tid < 64) sh.p.pflag[tid] = 0;
    __syncthreads();
    if (upper) {
        for (int i = tid; i < BATCH; i += 1024) {
            int rp = N_USER + pos[i] - k0;
            if ((unsigned)rp < 64u) sh.p.pflag[rp] = 1;
        }
    }
    const float* src = upper ? (ie + (size_t)(k0 - N_USER) * D) : (ue + (size_t)k0 * D);
    {
        int k = tid >> 4, ng = tid & 15;
        float4 v = *(const float4*)(src + (size_t)k * D + ng * 4);
        sh.p.tile[k][ng * 4 + 0] = v.x;
        sh.p.tile[k][ng * 4 + 1] = v.y;
        sh.p.tile[k][ng * 4 + 2] = v.z;
        sh.p.tile[k][ng * 4 + 3] = v.w;
        *(float4*)(g_ego + (size_t)(k0 + k) * D + ng * 4) = v;
    }
    __syncthreads();
    __nv_bfloat16 z = __float2bfloat16(0.f);
    {
        int n = tid >> 4, kg = tid & 15;
        int k = kg * 4;
        uint32_t vh[2], vl[2], vmh[2], vml[2];
#pragma unroll
        for (int j = 0; j < 2; ++j) {
            float x0 = sh.p.tile[k + 2 * j][n];
            float x1 = sh.p.tile[k + 2 * j + 1][n];
            __nv_bfloat16 h0 = __float2bfloat16(x0), h1 = __float2bfloat16(x1);
            __nv_bfloat16 l0 = __float2bfloat16(x0 - __bfloat162float(h0));
            __nv_bfloat16 l1 = __float2bfloat16(x1 - __bfloat162float(h1));
            __nv_bfloat162 hp = __halves2bfloat162(h0, h1);
            __nv_bfloat162 lp = __halves2bfloat162(l0, l1);
            vh[j] = *(uint32_t*)&hp; vl[j] = *(uint32_t*)&lp;
            bool f0 = sh.p.pflag[k + 2 * j] != 0, f1 = sh.p.pflag[k + 2 * j + 1] != 0;
            __nv_bfloat162 mhp = __halves2bfloat162(f0 ? h0 : z, f1 ? h1 : z);
            __nv_bfloat162 mlp = __halves2bfloat162(f0 ? l0 : z, f1 ? l1 : z);
            vmh[j] = *(uint32_t*)&mhp; vml[j] = *(uint32_t*)&mlp;
        }
        size_t o = (size_t)n * NTOT + k0 + k;
        *(uint2*)(g_eThi + o) = make_uint2(vh[0], vh[1]);
        *(uint2*)(g_eTlo + o) = make_uint2(vl[0], vl[1]);
        if (upper) {
            *(uint2*)(g_eMhi + o) = make_uint2(vmh[0], vmh[1]);
            *(uint2*)(g_eMlo + o) = make_uint2(vml[0], vml[1]);
        }
    }
}

// -------- 2. main GEMM: 32x32 warp tiles, 3-stage cp.async.cg pipeline --------
__global__ void __launch_bounds__(256, 2) k_main(const float* __restrict__ adj) {
    extern __shared__ char sm[];
    uint32_t smb = smem_u32(sm);
    const float** sRow = (const float**)(sm + ROWP_OFF);

    int tid = threadIdx.x, wid = tid >> 5, lane = tid & 31;
    int cF = g_cF, cU = g_cU;
    int bx = blockIdx.x;

    int slotBase, j0, cnt, split;
    size_t kbase;
    const int* list;
    const __nv_bfloat16 *bh, *bl;
    if (bx < F_ITEMS) {
        int tile = bx >> 4; split = bx & (NSPF - 1);
        if (tile * 128 >= cF) return;
        j0 = tile * 128; slotBase = j0; list = g_listF; cnt = cF;
        bh = g_eThi; bl = g_eTlo;
        kbase = (size_t)split * KSPL;
    } else {
        int u = bx - F_ITEMS;
        int tile = u >> 3; split = u & (NSPU - 1);
        if (tile * 128 >= cU) return;
        j0 = tile * 128; slotBase = UBASE + j0; list = g_listU; cnt = cU;
        bh = g_eMhi; bl = g_eMlo;
        kbase = (size_t)N_USER + (size_t)split * KSPL;
    }

    if (tid < 128) {
        int j = j0 + tid; if (j >= cnt) j = cnt - 1;
        sRow[tid] = adj + (size_t)list[j] * NTOT + kbase;
    }
    __syncthreads();

    // ---- A staging map ----
    int r0s = tid >> 3, chs = tid & 7;
    const float* apj[4];
#pragma unroll
    for (int j = 0; j < 4; ++j) apj[j] = sRow[r0s + 32 * j] + chs * 4;
    uint32_t aDst = smb + A_OFF + (uint32_t)(r0s * ASTR + chs * 4) * 4;

    // ---- B staging map ----
    int bn = tid >> 2, bc = tid & 3;
    const __nv_bfloat16* bsrcH = bh + kbase + (size_t)bn * NTOT + bc * 8;
    const __nv_bfloat16* bsrcL = bl + kbase + (size_t)bn * NTOT + bc * 8;
    uint32_t bDstH = smb + BH_OFF + (uint32_t)(bn * BSTR + bc * 8) * 2;
    uint32_t bDstL = smb + BL_OFF + (uint32_t)(bn * BSTR + bc * 8) * 2;

    // ---- compute-side addressing: warp tile = 32 rows x 32 cols ----
    int mg = wid >> 1;
    int nh = wid & 1;
    const float* aBase = (const float*)(sm + A_OFF);
    int frow0 = mg * 32 + (lane >> 2);
    const float* aR0 = aBase + frow0 * ASTR + (lane & 3) * 2;
    const float* aR1 = aR0 + 8 * ASTR;
    const float* aR2 = aR0 + 16 * ASTR;
    const float* aR3 = aR0 + 24 * ASTR;
    uint32_t bLm = (uint32_t)(((nh * 32 + (lane & 7) + ((lane >> 4) << 3)) * BSTR
                               + ((lane >> 3) & 1) * 8) * 2);

    float acc[2][4][4];
#pragma unroll
    for (int mb = 0; mb < 2; ++mb)
#pragma unroll
        for (int nb = 0; nb < 4; ++nb)
#pragma unroll
            for (int i = 0; i < 4; ++i) acc[mb][nb][i] = 0.f;

    // ---- prologue: stages 0,1 ----
#pragma unroll
    for (int s = 0; s < 2; ++s) {
        uint32_t ad = aDst + s * ASTAGE;
        size_t ko = (size_t)s * KT;
#pragma unroll
        for (int j = 0; j < 4; ++j) cp16cg(ad + j * (32 * ASTR * 4), apj[j] + ko);
        cp16cg(bDstH + s * BSTAGE, bsrcH + ko);
        cp16cg(bDstL + s * BSTAGE, bsrcL + ko);
        CP_COMMIT();
    }

    for (int kt = 0; kt < NKT; ++kt) {
        int buf = kt % NSTAGE;
        CP_WAIT(1);
        __syncthreads();
        if (kt + 2 < NKT) {
            int s = (kt + 2) % NSTAGE;
            uint32_t ad = aDst + s * ASTAGE;
            size_t ko = (size_t)(kt + 2) * KT;
#pragma unroll
            for (int j = 0; j < 4; ++j) cp16cg(ad + j * (32 * ASTR * 4), apj[j] + ko);
            cp16cg(bDstH + s * BSTAGE, bsrcH + ko);
            cp16cg(bDstL + s * BSTAGE, bsrcL + ko);
        }
        CP_COMMIT();

        int abufo = buf * (ASTAGE / 4);
        uint32_t bh_base = smb + BH_OFF + buf * BSTAGE + bLm;
        uint32_t bl_base = smb + BL_OFF + buf * BSTAGE + bLm;

#pragma unroll
        for (int ks = 0; ks < 2; ++ks) {
            int ko = ks * 16;
            uint32_t ahf[2][4], alf[2][4];
            {
                float2 x0 = *(const float2*)(aR0 + abufo + ko);
                float2 x1 = *(const float2*)(aR1 + abufo + ko);
                float2 x2 = *(const float2*)(aR0 + abufo + ko + 8);
                float2 x3 = *(const float2*)(aR1 + abufo + ko + 8);
                split2(x0, ahf[0][0], alf[0][0]);
                split2(x1, ahf[0][1], alf[0][1]);
                split2(x2, ahf[0][2], alf[0][2]);
                split2(x3, ahf[0][3], alf[0][3]);
                x0 = *(const float2*)(aR2 + abufo + ko);
                x1 = *(const float2*)(aR3 + abufo + ko);
                x2 = *(const float2*)(aR2 + abufo + ko + 8);
                x3 = *(const float2*)(aR3 + abufo + ko + 8);
                split2(x0, ahf[1][0], alf[1][0]);
                split2(x1, ahf[1][1], alf[1][1]);
                split2(x2, ahf[1][2], alf[1][2]);
                split2(x3, ahf[1][3], alf[1][3]);
            }
            uint32_t bhf[4][2], blf[4][2];
            {
                uint32_t r[4];
                ldmx4(r, bh_base + ks * 32);
                bhf[0][0] = r[0]; bhf[0][1] = r[1]; bhf[1][0] = r[2]; bhf[1][1] = r[3];
                ldmx4(r, bh_base + 16 * BSTR * 2 + ks * 32);
                bhf[2][0] = r[0]; bhf[2][1] = r[1]; bhf[3][0] = r[2]; bhf[3][1] = r[3];
                ldmx4(r, bl_base + ks * 32);
                blf[0][0] = r[0]; blf[0][1] = r[1]; blf[1][0] = r[2]; blf[1][1] = r[3];
                ldmx4(r, bl_base + 16 * BSTR * 2 + ks * 32);
                blf[2][0] = r[0]; blf[2][1] = r[1]; blf[3][0] = r[2]; blf[3][1] = r[3];
            }
#pragma unroll
            for (int mb = 0; mb < 2; ++mb)
#pragma unroll
                for (int nb = 0; nb < 4; ++nb) {
                    mma16816(acc[mb][nb], ahf[mb], bhf[nb]);
                    mma16816(acc[mb][nb], ahf[mb], blf[nb]);
                    mma16816(acc[mb][nb], alf[mb], bhf[nb]);
                }
        }
    }

    float* dst = g_part[split];
#pragma unroll
    for (int mb = 0; mb < 2; ++mb) {
        int r0 = slotBase + mg * 32 + mb * 16 + (lane >> 2);
#pragma unroll
        for (int nb = 0; nb < 4; ++nb) {
            int col = nh * 32 + nb * 8 + (lane & 3) * 2;
            *(float2*)(dst + (size_t)r0 * D + col)       = make_float2(acc[mb][nb][0], acc[mb][nb][1]);
            *(float2*)(dst + (size_t)(r0 + 8) * D + col) = make_float2(acc[mb][nb][2], acc[mb][nb][3]);
        }
    }
}

// -------- 3. gather: 8 threads/q, 2 float4 each; deterministic reduction --------
__global__ void k_gather(const float* __restrict__ adj,
                         const int* __restrict__ users, const int* __restrict__ pos,
                         const int* __restrict__ neg, float* __restrict__ out) {
    int t = blockIdx.x * 256 + threadIdx.x;    // t < 12288 * 8
    int q = t >> 3, j = t & 7;
    int ds0 = j * 4, ds1 = j * 4 + 32;
    int r;
    if (q < BATCH)          r = users[q];
    else if (q < 2 * BATCH) r = N_USER + pos[q - BATCH];
    else                    r = N_USER + neg[q - 2 * BATCH];
    int p = g_pos[r];
    size_t o0 = (size_t)p * D + ds0, o1 = (size_t)p * D + ds1;
    float4 s0 = make_float4(0.f, 0.f, 0.f, 0.f);
    float4 s1 = make_float4(0.f, 0.f, 0.f, 0.f);
    if (p < UBASE) {
#pragma unroll
        for (int k = 0; k < NSPF; ++k) {
            float4 v0 = *(const float4*)(g_part[k] + o0);
            float4 v1 = *(const float4*)(g_part[k] + o1);
            s0.x += v0.x; s0.y += v0.y; s0.z += v0.z; s0.w += v0.w;
            s1.x += v1.x; s1.y += v1.y; s1.z += v1.z; s1.w += v1.w;
        }
    } else {
#pragma unroll
        for (int k = 0; k < NSPU; ++k) {
            float4 v0 = *(const float4*)(g_part[k] + o0);
            float4 v1 = *(const float4*)(g_part[k] + o1);
            s0.x += v0.x; s0.y += v0.y; s0.z += v0.z; s0.w += v0.w;
            s1.x += v1.x; s1.y += v1.y; s1.z += v1.z; s1.w += v1.w;
        }
        int u0 = users[0];
        float a = adj[(size_t)r * NTOT + u0];
        float4 e0 = *(const float4*)(g_ego + (size_t)u0 * D + ds0);
        float4 e1 = *(const float4*)(g_ego + (size_t)u0 * D + ds1);
        s0.x += a * e0.x; s0.y += a * e0.y; s0.z += a * e0.z; s0.w += a * e0.w;
        s1.x += a * e1.x; s1.y += a * e1.y; s1.z += a * e1.z; s1.w += a * e1.w;
    }
    float4 eg0 = *(const float4*)(g_ego + (size_t)r * D + ds0);
    float4 eg1 = *(const float4*)(g_ego + (size_t)r * D + ds1);
    float4 r0, r1;
    r0.x = 0.25f * (eg0.x + 3.0f * s0.x);
    r0.y = 0.25f * (eg0.y + 3.0f * s0.y);
    r0.z = 0.25f * (eg0.z + 3.0f * s0.z);
    r0.w = 0.25f * (eg0.w + 3.0f * s0.w);
    r1.x = 0.25f * (eg1.x + 3.0f * s1.x);
    r1.y = 0.25f * (eg1.y + 3.0f * s1.y);
    r1.z = 0.25f * (eg1.z + 3.0f * s1.z);
    r1.w = 0.25f * (eg1.w + 3.0f * s1.w);
    *(float4*)(out + (size_t)q * D + ds0) = r0;
    *(float4*)(out + (size_t)q * D + ds1) = r1;
}

extern "C" void kernel_launch(void* const* d_in, const int* in_sizes, int n_in,
                              void* d_out, int out_size) {
    const float* adj   = (const float*)d_in[0];
    const float* ue    = (const float*)d_in[1];
    const float* ie    = (const float*)d_in[2];
    const int*   users = (const int*)d_in[3];
    const int*   pos   = (const int*)d_in[4];
    const int*   neg   = (const int*)d_in[5];
    float*       out   = (float*)d_out;

    cudaFuncSetAttribute(k_main, cudaFuncAttributeMaxDynamicSharedMemorySize, SM_TOTAL);

    k_prep<<<NPREB + 1, 1024>>>(ue, ie, users, pos, neg);
    k_main<<<F_ITEMS + U_ITEMS, 256, SM_TOTAL>>>(adj);
    k_gather<<<(6 * BATCH * D / 8) / 256, 256>>>(adj, users, pos, neg, out);
}